// round 14
// baseline (speedup 1.0000x reference)
#include <cuda_runtime.h>
#include <cuda_fp16.h>

#define DEC 256
#define CSW 385               // packed-word copy stride (odd -> bank rotation)
#define NSLOT 64
#define SSTR  16              // slot stride = 16 u64 = 128B (distinct LTS lines)
#define FPSCALE 16777216.0f   // 2^24 fixed-point, deterministic accumulation

__device__ unsigned long long g_slots[NSLOT * SSTR];   // zero-init, self-reset
__device__ int                g_counter = 0;

static __device__ __forceinline__ unsigned HU(__half2 h) {
    return *reinterpret_cast<unsigned*>(&h);
}
static __device__ __forceinline__ __half2 UH(unsigned u) {
    return *reinterpret_cast<__half2*>(&u);
}

// One packed op = 2 pairs (row R vs ks k,k+1). nno/nnt hold negated own value
// broadcast in both halves; WO/WT are packed neighbor words (v_j, v_{j+1}).
// dO = o_j - o_i, dt = t_j - t_i (jointly negated vs ref -> invariant result).
#define PT2H(R, WO, WT)                                                       \
    {                                                                         \
        __half2 dO2 = __hadd2((WO), nno##R);                                  \
        __half2 dt2 = __hadd2((WT), nnt##R);                                  \
        __half2 x2  = UH(HU(dO2) ^ (HU(dt2) & 0x80008000u));                  \
        __half2 h2  = __hmax2(__hadd2(x2, one2), zero2);                      \
        __half2 m2  = __hgt2(__habs2(dt2), thr2);                             \
        acc##R = __hfma2(h2, m2, acc##R);                                     \
    }

// Masked variant for the last packed step (hi half may be k=128).
#define PT2HM(R, WO, WT)                                                      \
    {                                                                         \
        __half2 dO2 = __hadd2((WO), nno##R);                                  \
        __half2 dt2 = __hadd2((WT), nnt##R);                                  \
        __half2 x2  = UH(HU(dO2) ^ (HU(dt2) & 0x80008000u));                  \
        __half2 h2  = __hmax2(__hadd2(x2, one2), zero2);                      \
        __half2 m2  = __hmul2(__hgt2(__habs2(dt2), thr2), em2);               \
        acc##R = __hfma2(h2, m2, acc##R);                                     \
    }

#define STEPK(KAP)                                                            \
    PT2H(0, po[0 + 2 * (KAP)], pq[0 + 2 * (KAP)])                             \
    PT2H(1, po[1 + 2 * (KAP)], pq[1 + 2 * (KAP)])                             \
    PT2H(2, po[2 + 2 * (KAP)], pq[2 + 2 * (KAP)])                             \
    PT2H(3, po[3 + 2 * (KAP)], pq[3 + 2 * (KAP)])

__global__ void __launch_bounds__(256)
rank_loss_fused(const float* __restrict__ inp, const float* __restrict__ tm,
                float* __restrict__ out, float scale) {
    __shared__ float   s_fo[520], s_ft[520];        // fp32 scratch (dup to 511)
    __shared__ __half2 s_ho[4 * CSW], s_ht[4 * CSW];// 4 copies, packed (vj,vj+1)
    __shared__ float   warpsum[8];
    __shared__ unsigned long long s_red[NSLOT];
    __shared__ int s_isLast;

    const int g    = blockIdx.x >> 1;   // group
    const int half = blockIdx.x & 1;    // k-tile: 0 -> k 1..64, 1 -> 65..128
    const int tid  = threadIdx.x;
    const int base = g * DEC;

    {
        float o = inp[base + tid];
        float t = tm[base + tid];
        s_fo[tid] = o;  s_fo[tid + DEC] = o;
        s_ft[tid] = t;  s_ft[tid + DEC] = t;
    }
    __syncthreads();

    // Build packed half2 words j = tid and j = tid+128 (covers j = 0..383).
    {
        __half2 a0 = __floats2half2_rn(s_fo[tid], s_fo[tid + 1]);
        __half2 a1 = __floats2half2_rn(s_fo[tid + 128], s_fo[tid + 129]);
        __half2 b0 = __floats2half2_rn(s_ft[tid], s_ft[tid + 1]);
        __half2 b1 = __floats2half2_rn(s_ft[tid + 128], s_ft[tid + 129]);
        #pragma unroll
        for (int c = 0; c < 4; ++c) {
            s_ho[c * CSW + tid]       = a0;
            s_ho[c * CSW + tid + 128] = a1;
            s_ht[c * CSW + tid]       = b0;
            s_ht[c * CSW + tid + 128] = b1;
        }
    }

    // 4 k-subranges (16 each) x 64 row-quads.
    const int s    = tid >> 6;
    const int tau  = tid & 63;
    const int b    = tau * 4;                  // first owned row
    const int k0   = half * 64 + s * 16 + 1;   // k in [k0, k0+15], k0 odd
    const int copy = (tid >> 3) & 3;           // lane-octet -> bank residue

    // Own rows, negated, broadcast into both halves (from fp32 scratch).
    const __half2 nno0 = __half2half2(__float2half_rn(-s_fo[b + 0]));
    const __half2 nno1 = __half2half2(__float2half_rn(-s_fo[b + 1]));
    const __half2 nno2 = __half2half2(__float2half_rn(-s_fo[b + 2]));
    const __half2 nno3 = __half2half2(__float2half_rn(-s_fo[b + 3]));
    const __half2 nnt0 = __half2half2(__float2half_rn(-s_ft[b + 0]));
    const __half2 nnt1 = __half2half2(__float2half_rn(-s_ft[b + 1]));
    const __half2 nnt2 = __half2half2(__float2half_rn(-s_ft[b + 2]));
    const __half2 nnt3 = __half2half2(__float2half_rn(-s_ft[b + 3]));
    __syncthreads();

    const __half2* po = &s_ho[copy * CSW + b + k0];   // offsets r+2k: immediates
    const __half2* pq = &s_ht[copy * CSW + b + k0];

    const __half2 one2  = __float2half2_rn(1.0f);
    const __half2 zero2 = __float2half2_rn(0.0f);
    const __half2 thr2  = __float2half2_rn(0.1f);
    // Last packed step's hi half is k = k0+15; only k=128 (half==1 && tid>=224)
    // is restricted to rows < 128 -> mask hi half there.
    const __half2 em2 = __floats2half2_rn(1.0f,
                            (half && tid >= 224) ? 0.0f : 1.0f);

    __half2 acc0 = zero2, acc1 = zero2, acc2 = zero2, acc3 = zero2;

    STEPK(0) STEPK(1) STEPK(2) STEPK(3) STEPK(4) STEPK(5) STEPK(6)
    PT2HM(0, po[0 + 14], pq[0 + 14])
    PT2HM(1, po[1 + 14], pq[1 + 14])
    PT2HM(2, po[2 + 14], pq[2 + 14])
    PT2HM(3, po[3 + 14], pq[3 + 14])

    // Drain packed accumulators to fp32, block-reduce (fixed order).
    float ssum = ((__low2float(acc0) + __high2float(acc0)) +
                  (__low2float(acc1) + __high2float(acc1))) +
                 ((__low2float(acc2) + __high2float(acc2)) +
                  (__low2float(acc3) + __high2float(acc3)));
    const int lane = tid & 31;
    const int w    = tid >> 5;
    #pragma unroll
    for (int off = 16; off; off >>= 1)
        ssum += __shfl_xor_sync(0xFFFFFFFFu, ssum, off);
    if (lane == 0) warpsum[w] = ssum;
    __syncthreads();

    if (tid == 0) {
        float bsum = 0.0f;
        #pragma unroll
        for (int j = 0; j < 8; ++j) bsum += warpsum[j];
        unsigned long long q = (unsigned long long)llrintf(bsum * FPSCALE);
        // Spread slots: 64-way lower contention, still deterministic (int add).
        atomicAdd(&g_slots[(blockIdx.x & (NSLOT - 1)) * SSTR], q);
        __threadfence();
        int c = atomicAdd(&g_counter, 1);
        s_isLast = (c == (int)gridDim.x - 1);
    }
    __syncthreads();

    if (s_isLast) {
        if (tid < NSLOT) {
            unsigned long long v = atomicAdd(&g_slots[tid * SSTR], 0ULL);
            s_red[tid] = v;
            g_slots[tid * SSTR] = 0ULL;     // reset for next graph replay
        }
        __syncthreads();
        if (tid == 0) {
            unsigned long long tot = 0ULL;
            #pragma unroll
            for (int j = 0; j < NSLOT; ++j) tot += s_red[j];
            out[0] = (float)((double)tot * (1.0 / (double)FPSCALE) *
                             (double)scale);
            __threadfence();
            g_counter = 0;
        }
    }
}

extern "C" void kernel_launch(void* const* d_in, const int* in_sizes, int n_in,
                              void* d_out, int out_size) {
    const float* inp = (const float*)d_in[0];   // input, [B,1] fp32
    const float* tm  = (const float*)d_in[1];   // gdt_ts, [B]  fp32

    const int B = in_sizes[0];
    const int K = B / DEC;
    const int G = K - 1;                        // reference skips the last group
    const double N = (double)G * DEC * (DEC - 1);
    const float scale = (float)(2.0 / N);       // x2: unordered -> ordered pairs

    rank_loss_fused<<<2 * G, 256>>>(inp, tm, (float*)d_out, scale);
}

// round 17
// speedup vs baseline: 1.0457x; 1.0457x over previous
#include <cuda_runtime.h>
#include <cuda_fp16.h>

#define DEC 256
#define CSW 385               // packed-word copy stride; 385 % 32 == 1 -> copy c
                              // rotates banks by c, making stride-4 lanes conflict-free
#define NSLOT 64
#define SSTR  16              // slot stride = 16 u64 = 128B (distinct LTS lines)
#define FPSCALE 16777216.0f   // 2^24 fixed-point, deterministic accumulation

__device__ unsigned long long g_slots[NSLOT * SSTR];   // zero-init, self-reset
__device__ int                g_counter = 0;

static __device__ __forceinline__ unsigned HU(__half2 h) {
    return *reinterpret_cast<unsigned*>(&h);
}
static __device__ __forceinline__ __half2 UH(unsigned u) {
    return *reinterpret_cast<__half2*>(&u);
}

// One packed op = 2 pairs (row R vs ks k,k+1). nno/nnt: negated own value
// broadcast; WO/WT: packed neighbor words (v_j, v_{j+1}).
// dO = o_j - o_i, dt = t_j - t_i (jointly negated vs ref -> result invariant).
#define PTCORE(R, WO, WT, MEXTRA)                                             \
    {                                                                         \
        __half2 dO2 = __hadd2((WO), nno##R);                                  \
        __half2 dt2 = __hadd2((WT), nnt##R);                                  \
        __half2 x2  = UH(HU(dO2) ^ (HU(dt2) & 0x80008000u));                  \
        __half2 h2  = __hfma2_relu(x2, one2, one2);   /* max(x+1,0), 1 op */  \
        __half2 m2  = __hgt2(UH(HU(dt2) & 0x7FFF7FFFu), thr2);                \
        MEXTRA                                                                \
        acc##R = __hfma2(h2, m2, acc##R);                                     \
    }
#define PT2H(R, WO, WT)  PTCORE(R, WO, WT, )
#define PT2HM(R, WO, WT) PTCORE(R, WO, WT, m2 = __hmul2(m2, em2);)

// Even chain regs (eoX/etX) hold word positions {kap, kap+1} of the even
// parity chain; odd chain likewise. Rows 0,1 read position kap; rows 2,3
// read position kap+1 (word aliasing W(2,kap)==W(0,kap+1)). Positional
// phase A/B rotation -> zero register copies.
#define STEPA(KAP)                                                            \
    PT2H(0, eo0, et0) PT2H(1, oo0, ot0) PT2H(2, eo1, et1) PT2H(3, oo1, ot1)   \
    eo0 = PO[2*(KAP)+4]; et0 = PQ[2*(KAP)+4];                                 \
    oo0 = PO[2*(KAP)+5]; ot0 = PQ[2*(KAP)+5];
#define STEPB(KAP)                                                            \
    PT2H(0, eo1, et1) PT2H(1, oo1, ot1) PT2H(2, eo0, et0) PT2H(3, oo0, ot0)   \
    eo1 = PO[2*(KAP)+4]; et1 = PQ[2*(KAP)+4];                                 \
    oo1 = PO[2*(KAP)+5]; ot1 = PQ[2*(KAP)+5];

__global__ void __launch_bounds__(256)
rank_loss_fused(const float* __restrict__ inp, const float* __restrict__ tm,
                float* __restrict__ out, float scale) {
    __shared__ __half2 s_ho[4 * CSW], s_ht[4 * CSW]; // 4 copies, packed (vj,vj+1)
    __shared__ float   warpsum[8];
    __shared__ unsigned long long s_red[NSLOT];
    __shared__ int s_isLast;

    const int g    = blockIdx.x;        // one block per group, full k = 1..128
    const int tid  = threadIdx.x;
    const int base = g * DEC;

    // Pack directly from global: word tid = (v_tid, v_{(tid+1)&255}).
    {
        float o0 = inp[base + tid];
        float o1 = inp[base + ((tid + 1) & 255)];
        float t0 = tm[base + tid];
        float t1 = tm[base + ((tid + 1) & 255)];
        __half2 wo = __floats2half2_rn(o0, o1);
        __half2 wt = __floats2half2_rn(t0, t1);
        #pragma unroll
        for (int c = 0; c < 4; ++c) {
            s_ho[c * CSW + tid] = wo;
            s_ht[c * CSW + tid] = wt;
            if (tid < 128) {                     // dup words 256..383
                s_ho[c * CSW + tid + 256] = wo;
                s_ht[c * CSW + tid + 256] = wt;
            }
        }
    }
    __syncthreads();

    // 4 k-subranges (32 each) x 64 row-quads.
    const int s    = tid >> 6;
    const int tau  = tid & 63;
    const int b    = tau * 4;                  // first owned row
    const int k0   = s * 32 + 1;               // k in [k0, k0+31], odd k0
    const int copy = (tid >> 3) & 3;           // lane-octet -> bank rotation

    const __half2* PBo = &s_ho[copy * CSW + b];
    const __half2* PBt = &s_ht[copy * CSW + b];
    const __half2* PO  = PBo + k0;             // all further offsets immediate
    const __half2* PQ  = PBt + k0;

    // Own rows = lo halves of words b..b+3; negate, broadcast.
    const __half2 nno0 = __half2half2(__hneg(__low2half(PBo[0])));
    const __half2 nno1 = __half2half2(__hneg(__low2half(PBo[1])));
    const __half2 nno2 = __half2half2(__hneg(__low2half(PBo[2])));
    const __half2 nno3 = __half2half2(__hneg(__low2half(PBo[3])));
    const __half2 nnt0 = __half2half2(__hneg(__low2half(PBt[0])));
    const __half2 nnt1 = __half2half2(__hneg(__low2half(PBt[1])));
    const __half2 nnt2 = __half2half2(__hneg(__low2half(PBt[2])));
    const __half2 nnt3 = __half2half2(__hneg(__low2half(PBt[3])));

    const __half2 one2 = __float2half2_rn(1.0f);
    const __half2 thr2 = __float2half2_rn(0.1f);
    // Last step's hi half is k = k0+31 = 128 only for s==3; k=128 pairs are
    // counted for rows < 128 only -> mask hi iff s==3 && tau>=32 <=> tid>=224.
    const __half2 em2 = __floats2half2_rn(1.0f, (tid >= 224) ? 0.0f : 1.0f);

    __half2 acc0 = __float2half2_rn(0.0f), acc1 = acc0, acc2 = acc0, acc3 = acc0;

    // Prime window: even chain positions 0,1 (offsets 0,2), odd (1,3).
    __half2 eo0 = PO[0], et0 = PQ[0], eo1 = PO[2], et1 = PQ[2];
    __half2 oo0 = PO[1], ot0 = PQ[1], oo1 = PO[3], ot1 = PQ[3];

    STEPA(0)  STEPB(1)  STEPA(2)  STEPB(3)
    STEPA(4)  STEPB(5)  STEPA(6)  STEPB(7)
    STEPA(8)  STEPB(9)  STEPA(10) STEPB(11)
    STEPA(12) STEPB(13) STEPA(14)
    // kap = 15 (phase B), masked hi, no refill.
    PT2HM(0, eo1, et1) PT2HM(1, oo1, ot1)
    PT2HM(2, eo0, et0) PT2HM(3, oo0, ot0)

    // Drain to fp32, block-reduce (fixed order).
    float ssum = ((__low2float(acc0) + __high2float(acc0)) +
                  (__low2float(acc1) + __high2float(acc1))) +
                 ((__low2float(acc2) + __high2float(acc2)) +
                  (__low2float(acc3) + __high2float(acc3)));
    const int lane = tid & 31;
    const int w    = tid >> 5;
    #pragma unroll
    for (int off = 16; off; off >>= 1)
        ssum += __shfl_xor_sync(0xFFFFFFFFu, ssum, off);
    if (lane == 0) warpsum[w] = ssum;
    __syncthreads();

    if (tid == 0) {
        float bsum = 0.0f;
        #pragma unroll
        for (int j = 0; j < 8; ++j) bsum += warpsum[j];
        unsigned long long q = (unsigned long long)llrintf(bsum * FPSCALE);
        // 64 spread slots: ~8 adds/slot, deterministic (integer adds commute).
        atomicAdd(&g_slots[(blockIdx.x & (NSLOT - 1)) * SSTR], q);
        __threadfence();
        int c = atomicAdd(&g_counter, 1);
        s_isLast = (c == (int)gridDim.x - 1);
    }
    __syncthreads();

    if (s_isLast) {
        if (tid < NSLOT) {
            unsigned long long v = atomicAdd(&g_slots[tid * SSTR], 0ULL);
            s_red[tid] = v;
            g_slots[tid * SSTR] = 0ULL;     // reset for next graph replay
        }
        __syncthreads();
        if (tid == 0) {
            unsigned long long tot = 0ULL;
            #pragma unroll
            for (int j = 0; j < NSLOT; ++j) tot += s_red[j];
            out[0] = (float)((double)tot * (1.0 / (double)FPSCALE) *
                             (double)scale);
            __threadfence();
            g_counter = 0;
        }
    }
}

extern "C" void kernel_launch(void* const* d_in, const int* in_sizes, int n_in,
                              void* d_out, int out_size) {
    const float* inp = (const float*)d_in[0];   // input, [B,1] fp32
    const float* tm  = (const float*)d_in[1];   // gdt_ts, [B]  fp32

    const int B = in_sizes[0];
    const int K = B / DEC;
    const int G = K - 1;                        // reference skips the last group
    const double N = (double)G * DEC * (DEC - 1);
    const float scale = (float)(2.0 / N);       // x2: unordered -> ordered pairs

    rank_loss_fused<<<G, 256>>>(inp, tm, (float*)d_out, scale);
}